// round 5
// baseline (speedup 1.0000x reference)
#include <cuda_runtime.h>
#include <stdint.h>

#define N_NODES 100000
#define F_IN    128
#define H_DIM   16
#define C_OUT   40
#define N_EDGES 3200000

// ---- scratch (no cudaMalloc allowed); 16B-aligned for float4 / red.v4 ----
__device__ __align__(16) float g_dinv[N_NODES];          // deg -> rsqrt(deg)
__device__ __align__(16) float g_h1  [N_NODES * H_DIM];  // x@W1; reused as agg2
__device__ __align__(16) float g_agg1[N_NODES * H_DIM];  // layer1 agg; bias+relu in place
__device__ __align__(16) int   g_src [N_EDGES];
__device__ __align__(16) int   g_dst [N_EDGES];
__device__ __align__(16) float g_norm[N_EDGES];
__device__ int g_is32;                                    // 1 if edge_index is int32

__device__ __forceinline__ void red4(float* addr, float a, float b, float c, float d) {
    asm volatile("red.global.add.v4.f32 [%0], {%1,%2,%3,%4};"
                 :: "l"(addr), "f"(a), "f"(b), "f"(c), "f"(d) : "memory");
}

// fetch edge index element robust to int32/int64 storage
__device__ __forceinline__ int edge_idx(const void* ei, long long elem, int is32) {
    if (is32) return ((const int*)ei)[elem];
    return (int)((const long long*)ei)[elem];
}

// 0) dtype probe: if any of the first 4096 int64-interpreted values is out of
//    [0, N_NODES), the buffer must be int32. (Random int32 pairs read as int64
//    are astronomically unlikely to all land in-range.)
__global__ void k_probe(const long long* __restrict__ ei) {
    int i = blockIdx.x * blockDim.x + threadIdx.x;
    if (i == 0) g_is32 = 0;          // written before any read: grid of 1 block? no --
    // use a separate init below instead; here only flag bad values.
    long long v = ei[i];
    if (v < 0 || v >= (long long)N_NODES) g_is32 = 1;   // idempotent store, race-safe
}
__global__ void k_probe_init() { g_is32 = 0; }

// 1) deg[i] = 1 (self-loop)
__global__ void k_init_deg() {
    int i = blockIdx.x * blockDim.x + threadIdx.x;
    if (i < N_NODES) g_dinv[i] = 1.0f;
}

// 2) count degree over dst, cache dst as int32
__global__ void k_count(const void* __restrict__ ei) {
    int e = blockIdx.x * blockDim.x + threadIdx.x;
    if (e >= N_EDGES) return;
    int d = edge_idx(ei, (long long)N_EDGES + e, g_is32);   // dst row = second E block
    g_dst[e] = d;
    atomicAdd(&g_dinv[d], 1.0f);
}

// 3) dinv = rsqrt(deg)
__global__ void k_rsqrt() {
    int i = blockIdx.x * blockDim.x + threadIdx.x;
    if (i < N_NODES) g_dinv[i] = rsqrtf(g_dinv[i]);
}

// 4) cache src as int32, precompute norm = dinv[src]*dinv[dst]
__global__ void k_prep(const void* __restrict__ ei) {
    int e = blockIdx.x * blockDim.x + threadIdx.x;
    if (e >= N_EDGES) return;
    int s = edge_idx(ei, e, g_is32);                        // src row = first E block
    g_src[e] = s;
    g_norm[e] = g_dinv[s] * g_dinv[g_dst[e]];
}

// 5) h1 = x @ W1   ([N,128] @ [128,16]), W1 staged in smem
__global__ void k_gemm1(const float* __restrict__ x, const float* __restrict__ W) {
    __shared__ float Ws[F_IN * H_DIM];
    for (int i = threadIdx.x; i < F_IN * H_DIM; i += blockDim.x) Ws[i] = W[i];
    __syncthreads();
    int n = blockIdx.x * blockDim.x + threadIdx.x;
    if (n >= N_NODES) return;
    float acc[H_DIM];
#pragma unroll
    for (int c = 0; c < H_DIM; c++) acc[c] = 0.0f;
    const float4* xr = (const float4*)(x + (size_t)n * F_IN);
#pragma unroll 4
    for (int j = 0; j < F_IN / 4; j++) {
        float4 v = __ldg(&xr[j]);
        const float* w0 = &Ws[(4 * j) * H_DIM];
#pragma unroll
        for (int c = 0; c < H_DIM; c++) {
            float a = acc[c];
            a = fmaf(v.x, w0[c], a);
            a = fmaf(v.y, w0[H_DIM + c], a);
            a = fmaf(v.z, w0[2 * H_DIM + c], a);
            a = fmaf(v.w, w0[3 * H_DIM + c], a);
            acc[c] = a;
        }
    }
    float4* hp = (float4*)(g_h1 + (size_t)n * H_DIM);
    hp[0] = make_float4(acc[0], acc[1], acc[2], acc[3]);
    hp[1] = make_float4(acc[4], acc[5], acc[6], acc[7]);
    hp[2] = make_float4(acc[8], acc[9], acc[10], acc[11]);
    hp[3] = make_float4(acc[12], acc[13], acc[14], acc[15]);
}

// 6/8) self-loop init: agg[n] = h[n] * dinv[n]^2
// LAYER1: h = g_h1,   agg = g_agg1   |   LAYER2: h = g_agg1, agg = g_h1
template<bool LAYER1>
__global__ void k_self() {
    int n = blockIdx.x * blockDim.x + threadIdx.x;
    if (n >= N_NODES) return;
    const float* h   = LAYER1 ? g_h1   : g_agg1;
    float*       agg = LAYER1 ? g_agg1 : g_h1;
    float w = g_dinv[n];
    w *= w;
    const float4* hp = (const float4*)(h + (size_t)n * H_DIM);
    float4*       ap = (float4*)(agg + (size_t)n * H_DIM);
#pragma unroll
    for (int i = 0; i < 4; i++) {
        float4 v = hp[i];
        v.x *= w; v.y *= w; v.z *= w; v.w *= w;
        ap[i] = v;
    }
}

// 7/9) edge scatter: agg[dst] += h[src] * norm (v4 reductions, L2-resident)
template<bool LAYER1>
__global__ void k_scatter() {
    int e = blockIdx.x * blockDim.x + threadIdx.x;
    if (e >= N_EDGES) return;
    const float* h   = LAYER1 ? g_h1   : g_agg1;
    float*       agg = LAYER1 ? g_agg1 : g_h1;
    int s = g_src[e];
    int d = g_dst[e];
    float w = g_norm[e];
    const float4* hp = (const float4*)(h + (size_t)s * H_DIM);
    float4 v0 = __ldg(&hp[0]);
    float4 v1 = __ldg(&hp[1]);
    float4 v2 = __ldg(&hp[2]);
    float4 v3 = __ldg(&hp[3]);
    float* ap = agg + (size_t)d * H_DIM;
    red4(ap +  0, v0.x * w, v0.y * w, v0.z * w, v0.w * w);
    red4(ap +  4, v1.x * w, v1.y * w, v1.z * w, v1.w * w);
    red4(ap +  8, v2.x * w, v2.y * w, v2.z * w, v2.w * w);
    red4(ap + 12, v3.x * w, v3.y * w, v3.z * w, v3.w * w);
}

// bias + relu, in place on agg1
__global__ void k_relu(const float* __restrict__ b1) {
    int i = blockIdx.x * blockDim.x + threadIdx.x;
    if (i >= N_NODES * H_DIM) return;
    float b = __ldg(&b1[i & (H_DIM - 1)]);
    g_agg1[i] = fmaxf(g_agg1[i] + b, 0.0f);
}

// 10) out = agg2 @ W2 + b2   ([N,16] @ [16,40]); agg2 lives in g_h1
__global__ void k_gemm2(const float* __restrict__ W2, const float* __restrict__ b2,
                        float* __restrict__ out) {
    __shared__ float Ws[H_DIM * C_OUT];
    __shared__ float Bs[C_OUT];
    for (int i = threadIdx.x; i < H_DIM * C_OUT; i += blockDim.x) Ws[i] = W2[i];
    for (int i = threadIdx.x; i < C_OUT; i += blockDim.x) Bs[i] = b2[i];
    __syncthreads();
    int t = blockIdx.x * blockDim.x + threadIdx.x;
    if (t >= N_NODES * C_OUT) return;
    int n = t / C_OUT;
    int c = t - n * C_OUT;
    const float* r = g_h1 + (size_t)n * H_DIM;
    float acc = Bs[c];
#pragma unroll
    for (int k = 0; k < H_DIM; k++)
        acc = fmaf(r[k], Ws[k * C_OUT + c], acc);
    out[t] = acc;
}

extern "C" void kernel_launch(void* const* d_in, const int* in_sizes, int n_in,
                              void* d_out, int out_size) {
    const float* x   = (const float*)d_in[0];
    const void*  ei  = d_in[1];                 // [2, E], int32 OR int64 storage
    const float* W1  = (const float*)d_in[2];
    const float* b1  = (const float*)d_in[3];
    const float* W2  = (const float*)d_in[4];
    const float* b2  = (const float*)d_in[5];
    float*       out = (float*)d_out;

    const int T = 256;
    const int gN  = (N_NODES + T - 1) / T;
    const int gE  = (N_EDGES + T - 1) / T;
    const int gNH = (N_NODES * H_DIM + T - 1) / T;
    const int gNC = (N_NODES * C_OUT + T - 1) / T;

    // dtype probe: reading 4096 int64 = 32KB, within the buffer either way
    k_probe_init<<<1, 1>>>();
    k_probe<<<4096 / 256, 256>>>((const long long*)ei);

    k_init_deg<<<gN, T>>>();
    k_count<<<gE, T>>>(ei);
    k_rsqrt<<<gN, T>>>();
    k_prep<<<gE, T>>>(ei);

    k_gemm1<<<(N_NODES + 127) / 128, 128>>>(x, W1);

    // layer 1 aggregation
    k_self<true><<<gN, T>>>();
    k_scatter<true><<<gE, T>>>();
    k_relu<<<gNH, T>>>(b1);

    // layer 2 aggregation (agg2 reuses g_h1)
    k_self<false><<<gN, T>>>();
    k_scatter<false><<<gE, T>>>();

    k_gemm2<<<gNC, T>>>(W2, b2, out);
}

// round 6
// speedup vs baseline: 1.8090x; 1.8090x over previous
#include <cuda_runtime.h>
#include <stdint.h>

#define N_NODES 100000
#define F_IN    128
#define H_DIM   16
#define C_OUT   40
#define N_EDGES 3200000
#define SCAN_B  256
#define NB      ((N_NODES + SCAN_B - 1) / SCAN_B)   // 391 blocks

// ---- scratch (no cudaMalloc allowed) ----
__device__ int   g_is32;
__device__ int   g_deg [N_NODES];
__device__ int   g_off [N_NODES + 1];
__device__ int   g_cur [N_NODES];
__device__ int   g_bsum[512];
__device__ int   g_bsumoff[512];
__device__ float g_dinv[N_NODES];
__device__ int   g_dst [N_EDGES];
__device__ int   g_esrc[N_EDGES];                       // CSR: src ids grouped by dst
__device__ __align__(16) float g_hs_a[N_NODES * H_DIM]; // (x@W1)*dinv ; later agg2
__device__ __align__(16) float g_hs_b[N_NODES * H_DIM]; // relu(agg1+b1)*dinv

__device__ __forceinline__ float4 f4add(float4 a, float4 b) {
    return make_float4(a.x + b.x, a.y + b.y, a.z + b.z, a.w + b.w);
}

// edge index fetch robust to int32/int64 storage
__device__ __forceinline__ int edge_idx(const void* ei, long long elem, int is32) {
    if (is32) return ((const int*)ei)[elem];
    return (int)((const long long*)ei)[elem];
}

// ---- dtype probe: any out-of-range int64 view => storage is int32 ----
__global__ void k_probe_init() { g_is32 = 0; }
__global__ void k_probe(const long long* __restrict__ ei) {
    int i = blockIdx.x * blockDim.x + threadIdx.x;
    long long v = ei[i];
    if (v < 0 || v >= (long long)N_NODES) g_is32 = 1;
}

__global__ void k_deg_init() {
    int i = blockIdx.x * blockDim.x + threadIdx.x;
    if (i < N_NODES) g_deg[i] = 0;
}

// degree histogram over dst + cache dst as int32
__global__ void k_count(const void* __restrict__ ei) {
    int e = blockIdx.x * blockDim.x + threadIdx.x;
    if (e >= N_EDGES) return;
    int d = edge_idx(ei, (long long)N_EDGES + e, g_is32);
    g_dst[e] = d;
    atomicAdd(&g_deg[d], 1);
}

// ---- 3-kernel exclusive scan over g_deg -> g_off ----
__global__ void k_scan1() {
    __shared__ int s[SCAN_B];
    int t = threadIdx.x;
    int i = blockIdx.x * SCAN_B + t;
    int v = (i < N_NODES) ? g_deg[i] : 0;
    s[t] = v;
    __syncthreads();
#pragma unroll
    for (int off = 1; off < SCAN_B; off <<= 1) {
        int y = (t >= off) ? s[t - off] : 0;
        __syncthreads();
        s[t] += y;
        __syncthreads();
    }
    if (i < N_NODES) g_off[i] = s[t] - v;          // exclusive, block-local
    if (t == SCAN_B - 1) g_bsum[blockIdx.x] = s[t]; // block total
}
__global__ void k_scan2() {
    __shared__ int s[512];
    int t = threadIdx.x;
    int v = (t < NB) ? g_bsum[t] : 0;
    s[t] = v;
    __syncthreads();
#pragma unroll
    for (int off = 1; off < 512; off <<= 1) {
        int y = (t >= off) ? s[t - off] : 0;
        __syncthreads();
        s[t] += y;
        __syncthreads();
    }
    g_bsumoff[t] = s[t] - v;                        // exclusive block offsets
}
__global__ void k_scan3() {
    int i = blockIdx.x * blockDim.x + threadIdx.x;
    if (i >= N_NODES) return;
    int val = g_off[i] + g_bsumoff[i >> 8];         // SCAN_B == 256
    g_off[i] = val;
    g_cur[i] = val;
    if (i == 0) g_off[N_NODES] = N_EDGES;
}

__global__ void k_dinv() {
    int i = blockIdx.x * blockDim.x + threadIdx.x;
    if (i < N_NODES) g_dinv[i] = rsqrtf((float)(g_deg[i] + 1)); // +1 self-loop
}

// bucket fill: CSR src list grouped by dst
__global__ void k_fill(const void* __restrict__ ei) {
    int e = blockIdx.x * blockDim.x + threadIdx.x;
    if (e >= N_EDGES) return;
    int s = edge_idx(ei, e, g_is32);
    int d = g_dst[e];
    int pos = atomicAdd(&g_cur[d], 1);
    g_esrc[pos] = s;
}

// h1 = (x @ W1) * dinv[n]   ([N,128]@[128,16]), W1 in smem
__global__ void k_gemm1(const float* __restrict__ x, const float* __restrict__ W) {
    __shared__ float Ws[F_IN * H_DIM];
    for (int i = threadIdx.x; i < F_IN * H_DIM; i += blockDim.x) Ws[i] = W[i];
    __syncthreads();
    int n = blockIdx.x * blockDim.x + threadIdx.x;
    if (n >= N_NODES) return;
    float acc[H_DIM];
#pragma unroll
    for (int c = 0; c < H_DIM; c++) acc[c] = 0.0f;
    const float4* xr = (const float4*)(x + (size_t)n * F_IN);
#pragma unroll 4
    for (int j = 0; j < F_IN / 4; j++) {
        float4 v = __ldg(&xr[j]);
        const float* w0 = &Ws[(4 * j) * H_DIM];
#pragma unroll
        for (int c = 0; c < H_DIM; c++) {
            float a = acc[c];
            a = fmaf(v.x, w0[c], a);
            a = fmaf(v.y, w0[H_DIM + c], a);
            a = fmaf(v.z, w0[2 * H_DIM + c], a);
            a = fmaf(v.w, w0[3 * H_DIM + c], a);
            acc[c] = a;
        }
    }
    float w = g_dinv[n];
    float4* hp = (float4*)(g_hs_a + (size_t)n * H_DIM);
    hp[0] = make_float4(acc[0] * w, acc[1] * w, acc[2] * w, acc[3] * w);
    hp[1] = make_float4(acc[4] * w, acc[5] * w, acc[6] * w, acc[7] * w);
    hp[2] = make_float4(acc[8] * w, acc[9] * w, acc[10] * w, acc[11] * w);
    hp[3] = make_float4(acc[12] * w, acc[13] * w, acc[14] * w, acc[15] * w);
}

// Gather aggregation. thread = (node, float4 chunk). No atomics.
// agg[n] = dinv[n] * (hs[n] + sum_{s in N(n)} hs[s])
// LAYER1: in g_hs_a, out g_hs_b = relu(agg + b1) * dinv
// LAYER2: in g_hs_b, out g_hs_a = agg            (bias b2 in gemm2)
template<bool LAYER1>
__global__ void k_agg(const float* __restrict__ b1) {
    int tid = blockIdx.x * blockDim.x + threadIdx.x;
    if (tid >= N_NODES * 4) return;
    int n = tid >> 2;
    int c = tid & 3;
    const float4* hs = (const float4*)(LAYER1 ? g_hs_a : g_hs_b);

    float4 a0 = hs[n * 4 + c];   // self-loop term (already *dinv[n])
    float4 a1 = make_float4(0.f, 0.f, 0.f, 0.f);

    int j   = g_off[n];
    int end = g_off[n + 1];
    for (; j + 2 <= end; j += 2) {
        int s0 = g_esrc[j];
        int s1 = g_esrc[j + 1];
        float4 v0 = __ldg(&hs[s0 * 4 + c]);
        float4 v1 = __ldg(&hs[s1 * 4 + c]);
        a0 = f4add(a0, v0);
        a1 = f4add(a1, v1);
    }
    if (j < end) {
        int s0 = g_esrc[j];
        a0 = f4add(a0, __ldg(&hs[s0 * 4 + c]));
    }
    float w = g_dinv[n];
    float4 r = f4add(a0, a1);
    r.x *= w; r.y *= w; r.z *= w; r.w *= w;
    if (LAYER1) {
        float4 bb = __ldg(&((const float4*)b1)[c]);
        r.x = fmaxf(r.x + bb.x, 0.f) * w;
        r.y = fmaxf(r.y + bb.y, 0.f) * w;
        r.z = fmaxf(r.z + bb.z, 0.f) * w;
        r.w = fmaxf(r.w + bb.w, 0.f) * w;
        ((float4*)g_hs_b)[n * 4 + c] = r;
    } else {
        ((float4*)g_hs_a)[n * 4 + c] = r;
    }
}

// out = agg2 @ W2 + b2   ([N,16]@[16,40]); node per thread
__global__ void k_gemm2(const float* __restrict__ W2, const float* __restrict__ b2,
                        float* __restrict__ out) {
    __shared__ float Ws[H_DIM * C_OUT];
    __shared__ float Bs[C_OUT];
    for (int i = threadIdx.x; i < H_DIM * C_OUT; i += blockDim.x) Ws[i] = W2[i];
    for (int i = threadIdx.x; i < C_OUT; i += blockDim.x) Bs[i] = b2[i];
    __syncthreads();
    int n = blockIdx.x * blockDim.x + threadIdx.x;
    if (n >= N_NODES) return;
    float h[H_DIM];
    const float4* hp = (const float4*)(g_hs_a + (size_t)n * H_DIM);
#pragma unroll
    for (int i = 0; i < 4; i++) {
        float4 v = hp[i];
        h[i * 4 + 0] = v.x; h[i * 4 + 1] = v.y; h[i * 4 + 2] = v.z; h[i * 4 + 3] = v.w;
    }
    float acc[C_OUT];
#pragma unroll
    for (int c = 0; c < C_OUT; c++) acc[c] = Bs[c];
#pragma unroll
    for (int k = 0; k < H_DIM; k++) {
        float hv = h[k];
        const float* wr = &Ws[k * C_OUT];
#pragma unroll
        for (int c = 0; c < C_OUT; c++) acc[c] = fmaf(hv, wr[c], acc[c]);
    }
    float4* op = (float4*)(out + (size_t)n * C_OUT);   // 160B rows, 16B aligned
#pragma unroll
    for (int i = 0; i < C_OUT / 4; i++)
        op[i] = make_float4(acc[4 * i], acc[4 * i + 1], acc[4 * i + 2], acc[4 * i + 3]);
}

extern "C" void kernel_launch(void* const* d_in, const int* in_sizes, int n_in,
                              void* d_out, int out_size) {
    const float* x   = (const float*)d_in[0];
    const void*  ei  = d_in[1];                 // [2, E], int32 OR int64 storage
    const float* W1  = (const float*)d_in[2];
    const float* b1  = (const float*)d_in[3];
    const float* W2  = (const float*)d_in[4];
    const float* b2  = (const float*)d_in[5];
    float*       out = (float*)d_out;

    const int T  = 256;
    const int gN = (N_NODES + T - 1) / T;
    const int gE = (N_EDGES + T - 1) / T;
    const int g4 = (N_NODES * 4 + T - 1) / T;

    k_probe_init<<<1, 1>>>();
    k_probe<<<4096 / 256, 256>>>((const long long*)ei);

    // CSR build
    k_deg_init<<<gN, T>>>();
    k_count<<<gE, T>>>(ei);
    k_scan1<<<NB, SCAN_B>>>();
    k_scan2<<<1, 512>>>();
    k_scan3<<<gN, T>>>();
    k_dinv<<<gN, T>>>();
    k_fill<<<gE, T>>>(ei);

    // layer 1
    k_gemm1<<<(N_NODES + 127) / 128, 128>>>(x, W1);
    k_agg<true><<<g4, T>>>(b1);

    // layer 2
    k_agg<false><<<g4, T>>>(b1);

    k_gemm2<<<gN, T>>>(W2, b2, out);
}